// round 2
// baseline (speedup 1.0000x reference)
#include <cuda_runtime.h>

// Problem constants
#define BATCH   32
#define CIN     256
#define NPIX    4096          // 64*64
#define HEADS   4
#define DH      32
#define HID     128           // HEADS*DH
#define O3      384           // 3*HID
#define EPS     1e-5f

// ---------------------------------------------------------------------------
// Scratch (device globals: allocation-free)
// ---------------------------------------------------------------------------
__device__ float g_qkv [(size_t)BATCH * O3  * NPIX];   // 201 MB
__device__ float g_attn[(size_t)BATCH * HID * NPIX];   //  67 MB
__device__ float g_stats[BATCH * 2];                   // sum, sumsq per batch

// ---------------------------------------------------------------------------
// K0: zero the stats accumulators (must be deterministic per launch)
// ---------------------------------------------------------------------------
__global__ void k_zero_stats() {
    int i = threadIdx.x;
    if (i < BATCH * 2) g_stats[i] = 0.f;
}

// ---------------------------------------------------------------------------
// K1 / K3: batched SGEMM  C[z][m][n] = sum_k A[m][k] * B[z][k][n] (+bias)
// A shared across batch (weights). Register-tiled fp32.
// BM=128, BN=128, BK=16, TM=TN=8, 256 threads.
// If EPI: add bias[m] and accumulate per-batch sum/sumsq into g_stats.
// M, N, K compile-time; all tile-divisible for this problem.
// ---------------------------------------------------------------------------
template<int M, int N, int K, bool EPI>
__global__ __launch_bounds__(256, 2)
void k_sgemm(const float* __restrict__ A,
             const float* __restrict__ Bg,
             float*       __restrict__ Cg,
             const float* __restrict__ bias)
{
    constexpr int BM = 128, BN = 128, BK = 16, TM = 8, TN = 8;

    __shared__ float As[BK][BM + 1];   // stored transposed, padded
    __shared__ float Bs[BK][BN];

    const int tid  = threadIdx.x;
    const int trow = tid / (BN / TN);        // 0..15
    const int tcol = tid % (BN / TN);        // 0..15

    // global tile origin
    const int z = blockIdx.z;
    const float* Bp = Bg + (size_t)z * K * N + (size_t)blockIdx.x * BN;
    const float* Ap = A  + (size_t)blockIdx.y * BM * K;
    float*       Cp = Cg + (size_t)z * M * N;

    // A loader: float4 along K.  rows/step = 256/(BK/4) = 64
    const int aRow = tid / (BK / 4);          // 0..63
    const int aCol = (tid % (BK / 4)) * 4;    // 0,4,8,12
    // B loader: float4 along N.  rows/step = 256/(BN/4) = 8
    const int bRow = tid / (BN / 4);          // 0..7
    const int bCol = (tid % (BN / 4)) * 4;

    float acc[TM][TN];
    #pragma unroll
    for (int i = 0; i < TM; i++)
        #pragma unroll
        for (int j = 0; j < TN; j++) acc[i][j] = 0.f;

    float regM[TM], regN[TN];

    for (int k0 = 0; k0 < K; k0 += BK) {
        // --- load A tile (transposed into smem) ---
        #pragma unroll
        for (int i = 0; i < BM; i += 64) {
            float4 t = *(const float4*)&Ap[(size_t)(aRow + i) * K + aCol];
            As[aCol + 0][aRow + i] = t.x;
            As[aCol + 1][aRow + i] = t.y;
            As[aCol + 2][aRow + i] = t.z;
            As[aCol + 3][aRow + i] = t.w;
        }
        // --- load B tile ---
        #pragma unroll
        for (int i = 0; i < BK; i += 8) {
            *(float4*)&Bs[bRow + i][bCol] =
                *(const float4*)&Bp[(size_t)(bRow + i) * N + bCol];
        }
        __syncthreads();

        Ap += BK;
        Bp += (size_t)BK * N;

        #pragma unroll
        for (int k = 0; k < BK; k++) {
            #pragma unroll
            for (int i = 0; i < TM; i++) regM[i] = As[k][trow * TM + i];
            #pragma unroll
            for (int j = 0; j < TN; j++) regN[j] = Bs[k][tcol * TN + j];
            #pragma unroll
            for (int i = 0; i < TM; i++)
                #pragma unroll
                for (int j = 0; j < TN; j++)
                    acc[i][j] += regM[i] * regN[j];
        }
        __syncthreads();
    }

    // --- epilogue ---
    const int cRow0 = blockIdx.y * BM + trow * TM;
    const int cCol0 = blockIdx.x * BN + tcol * TN;
    float lsum = 0.f, lsq = 0.f;

    #pragma unroll
    for (int i = 0; i < TM; i++) {
        float bv = EPI ? bias[cRow0 + i] : 0.f;
        #pragma unroll
        for (int j = 0; j < TN; j += 4) {
            float4 v;
            v.x = acc[i][j + 0] + bv;
            v.y = acc[i][j + 1] + bv;
            v.z = acc[i][j + 2] + bv;
            v.w = acc[i][j + 3] + bv;
            if (EPI) {
                lsum += v.x + v.y + v.z + v.w;
                lsq  += v.x * v.x + v.y * v.y + v.z * v.z + v.w * v.w;
            }
            *(float4*)&Cp[(size_t)(cRow0 + i) * N + cCol0 + j] = v;
        }
    }

    if (EPI) {
        // block reduce (8 warps)
        __shared__ float rs[8], rq[8];
        #pragma unroll
        for (int off = 16; off; off >>= 1) {
            lsum += __shfl_xor_sync(0xffffffffu, lsum, off);
            lsq  += __shfl_xor_sync(0xffffffffu, lsq,  off);
        }
        const int lane = tid & 31, wid = tid >> 5;
        if (lane == 0) { rs[wid] = lsum; rq[wid] = lsq; }
        __syncthreads();
        if (tid == 0) {
            float s = 0.f, q = 0.f;
            #pragma unroll
            for (int w = 0; w < 8; w++) { s += rs[w]; q += rq[w]; }
            atomicAdd(&g_stats[2 * z + 0], s);
            atomicAdd(&g_stats[2 * z + 1], q);
        }
    }
}

// ---------------------------------------------------------------------------
// K2: fused attention core. One block per (head, batch), 1024 threads.
//   Phase 0: per-row max & exp-sum for k (softmax over n=4096)
//   Phase 1: context[d][e] = sum_n softmax_k[d][n] * v[e][n]
//   Phase 2: per-column softmax of q over d (32), out[e][n] = ctx^T q
// ---------------------------------------------------------------------------
__global__ __launch_bounds__(1024)
void k_attn()
{
    const int h = blockIdx.x, b = blockIdx.y;
    const int tid = threadIdx.x, lane = tid & 31, wid = tid >> 5;

    __shared__ float rowmax[32], rowinv[32];
    __shared__ float ks[32][128];
    __shared__ float vs[32][129];     // pad: avoid 32-way conflicts
    __shared__ float ctx[32][33];     // pad

    const float* qbase = g_qkv + ((size_t)b * O3 + 0 * HID + h * DH) * NPIX;
    const float* kbase = g_qkv + ((size_t)b * O3 + 1 * HID + h * DH) * NPIX;
    const float* vbase = g_qkv + ((size_t)b * O3 + 2 * HID + h * DH) * NPIX;

    // ---- Phase 0: warp `wid` handles k row d = wid ----
    {
        const float* kr = kbase + (size_t)wid * NPIX;
        float m = -1e30f;
        for (int n = lane; n < NPIX; n += 32) m = fmaxf(m, kr[n]);
        #pragma unroll
        for (int off = 16; off; off >>= 1)
            m = fmaxf(m, __shfl_xor_sync(0xffffffffu, m, off));
        float s = 0.f;
        for (int n = lane; n < NPIX; n += 32) s += __expf(kr[n] - m);
        #pragma unroll
        for (int off = 16; off; off >>= 1)
            s += __shfl_xor_sync(0xffffffffu, s, off);
        if (lane == 0) { rowmax[wid] = m; rowinv[wid] = 1.f / s; }
    }
    __syncthreads();

    // ---- Phase 1: context ----
    const int d = wid, e = lane;      // thread owns ctx[d][e]
    float acc = 0.f;
    for (int nc = 0; nc < NPIX; nc += 128) {
        #pragma unroll
        for (int t = tid; t < 32 * 128; t += 1024) {
            const int dd = t >> 7, j = t & 127;
            const size_t off = (size_t)dd * NPIX + nc + j;
            ks[dd][j] = __expf(kbase[off] - rowmax[dd]) * rowinv[dd];
            vs[dd][j] = vbase[off];
        }
        __syncthreads();
        #pragma unroll
        for (int j = 0; j < 128; j++)
            acc += ks[d][j] * vs[e][j];
        __syncthreads();
    }
    ctx[d][e] = acc;
    __syncthreads();

    // ---- Phase 2: q softmax (over d) + out = ctx^T * q ----
    const float scale = 0.17677669529663687f;   // 32^-0.5
    float* obase = g_attn + ((size_t)b * HID + h * DH) * NPIX;

    for (int n = tid; n < NPIX; n += 1024) {
        float q[32];
        float m = -1e30f;
        #pragma unroll
        for (int dd = 0; dd < 32; dd++) {
            q[dd] = qbase[(size_t)dd * NPIX + n];
            m = fmaxf(m, q[dd]);
        }
        float s = 0.f;
        #pragma unroll
        for (int dd = 0; dd < 32; dd++) { q[dd] = __expf(q[dd] - m); s += q[dd]; }
        const float inv = scale / s;
        #pragma unroll
        for (int dd = 0; dd < 32; dd++) q[dd] *= inv;

        #pragma unroll
        for (int ee = 0; ee < 32; ee++) {
            float o = 0.f;
            #pragma unroll
            for (int dd = 0; dd < 32; dd++) o += ctx[dd][ee] * q[dd];
            obase[(size_t)ee * NPIX + n] = o;
        }
    }
}

// ---------------------------------------------------------------------------
// K4: in-place GroupNorm-over-everything per batch + affine per channel
// ---------------------------------------------------------------------------
__global__ __launch_bounds__(256)
void k_gn(float* __restrict__ out,
          const float* __restrict__ gn_w,
          const float* __restrict__ gn_b)
{
    const size_t gid  = (size_t)blockIdx.x * blockDim.x + threadIdx.x;
    const size_t base = gid * 4;                         // float4 index
    const int b = (int)(base >> 20);                     // 256*4096 = 2^20
    const int c = (int)((base >> 12) & 255);             // 4096 = 2^12

    const float invN = 1.f / (256.f * 4096.f);
    const float mean = g_stats[2 * b + 0] * invN;
    const float var  = g_stats[2 * b + 1] * invN - mean * mean;
    const float r    = rsqrtf(var + EPS);
    const float w    = gn_w[c] * r;
    const float bb   = gn_b[c] - mean * w;

    float4 v = *(float4*)&out[base];
    v.x = v.x * w + bb;
    v.y = v.y * w + bb;
    v.z = v.z * w + bb;
    v.w = v.w * w + bb;
    *(float4*)&out[base] = v;
}

// ---------------------------------------------------------------------------
// Launch
// ---------------------------------------------------------------------------
extern "C" void kernel_launch(void* const* d_in, const int* in_sizes, int n_in,
                              void* d_out, int out_size)
{
    const float* x     = (const float*)d_in[0];
    const float* w_qkv = (const float*)d_in[1];
    const float* w_out = (const float*)d_in[2];
    const float* b_out = (const float*)d_in[3];
    const float* gn_w  = (const float*)d_in[4];
    const float* gn_b  = (const float*)d_in[5];
    float* out = (float*)d_out;

    float *p_qkv, *p_attn;
    cudaGetSymbolAddress((void**)&p_qkv,  g_qkv);
    cudaGetSymbolAddress((void**)&p_attn, g_attn);

    // K0: zero stats
    k_zero_stats<<<1, 64>>>();

    // K1: QKV projection  [384,256] x [256,4096] per batch
    k_sgemm<O3, NPIX, CIN, false>
        <<<dim3(NPIX / 128, O3 / 128, BATCH), 256>>>(w_qkv, x, p_qkv, nullptr);

    // K2: attention core (one block per head x batch)
    k_attn<<<dim3(HEADS, BATCH), 1024>>>();

    // K3: output projection + bias + stats  [256,128] x [128,4096] per batch
    k_sgemm<CIN, NPIX, HID, true>
        <<<dim3(NPIX / 128, CIN / 128, BATCH), 256>>>(w_out, p_attn, out, b_out);

    // K4: GroupNorm normalize in place
    k_gn<<<(BATCH * CIN * NPIX / 4) / 256, 256>>>(out, gn_w, gn_b);
}

// round 5
// speedup vs baseline: 1.2977x; 1.2977x over previous
#include <cuda_runtime.h>
#include <cstdint>

// Problem constants
#define BATCH   32
#define CIN     256
#define NPIX    4096          // 64*64
#define HEADS   4
#define DH      32
#define HID     128           // HEADS*DH
#define O3      384           // 3*HID
#define EPS     1e-5f

// ---------------------------------------------------------------------------
// Scratch (device globals: allocation-free)
// ---------------------------------------------------------------------------
__device__ float g_qkv [(size_t)BATCH * O3  * NPIX];   // 201 MB
__device__ float g_attn[(size_t)BATCH * HID * NPIX];   //  67 MB
__device__ float g_stats[BATCH * 2];                   // sum, sumsq per batch

__global__ void k_zero_stats() {
    int i = threadIdx.x;
    if (i < BATCH * 2) g_stats[i] = 0.f;
}

// ---------------------------------------------------------------------------
// tf32 helpers (all sm_80-baseline PTX: compiles at compute_103)
// ---------------------------------------------------------------------------
__device__ __forceinline__ float to_tf32(float x) {
    uint32_t u;
    asm("cvt.rna.tf32.f32 %0, %1;" : "=r"(u) : "f"(x));
    return __uint_as_float(u);
}
__device__ __forceinline__ void mma_tf32(float c[4],
                                         const uint32_t a[4],
                                         const uint32_t b[2]) {
    asm volatile(
        "mma.sync.aligned.m16n8k8.row.col.f32.tf32.tf32.f32 "
        "{%0,%1,%2,%3}, {%4,%5,%6,%7}, {%8,%9}, {%0,%1,%2,%3};"
        : "+f"(c[0]), "+f"(c[1]), "+f"(c[2]), "+f"(c[3])
        : "r"(a[0]), "r"(a[1]), "r"(a[2]), "r"(a[3]),
          "r"(b[0]), "r"(b[1]));
}
// smem column swizzle: conflict-free for both the staging STS pattern and the
// fragment LDS pattern (k = lane&3 rows, m/n = lane>>2 cols).
__device__ __forceinline__ int swz(int k) {
    return (((k & 3) ^ ((k >> 2) & 3)) << 3);   // {0,8,16,24}
}

// ---------------------------------------------------------------------------
// tf32 tensor-core GEMM:  C[z][M][4096] = A[M,K] * B[z][K,4096]  (+bias,+stats)
// CTA tile 128x128, BK=16, 8 warps (2m x 4n), warp tile 64x32.
// ---------------------------------------------------------------------------
template<int K, int M, bool EPI>
__global__ __launch_bounds__(256)
void k_mma(const float* __restrict__ A, const float* __restrict__ Bg,
           float* __restrict__ Cg, const float* __restrict__ bias)
{
    __shared__ float As[2][16][128];
    __shared__ float Bs[2][16][128];

    const int tid  = threadIdx.x, lane = tid & 31, wid = tid >> 5;
    const int wm   = wid >> 2, wn = wid & 3;
    const int tq   = lane & 3, gp = lane >> 2;
    const int bx   = blockIdx.x, mt = blockIdx.y, z = blockIdx.z;

    const float* Ap = A  + (size_t)mt * 128 * K;
    const float* Bp = Bg + (size_t)z * K * NPIX + bx * 128;

    // loader indices
    const int am = tid & 127;          // A row (m)
    const int ak = (tid >> 7) * 8;     // A col base {0,8}
    const int bk = tid >> 5;           // B row (k) 0..7
    const int bn = lane * 4;           // B col (n)

    float acc[4][4][4];
    #pragma unroll
    for (int i = 0; i < 4; i++)
        #pragma unroll
        for (int j = 0; j < 4; j++)
            #pragma unroll
            for (int r = 0; r < 4; r++) acc[i][j][r] = 0.f;

    float4 ra[2], rb[2];

    auto ldg = [&](int t) {
        #pragma unroll
        for (int j = 0; j < 2; j++)
            ra[j] = *(const float4*)(Ap + (size_t)am * K + t * 16 + ak + j * 4);
        #pragma unroll
        for (int r = 0; r < 2; r++)
            rb[r] = *(const float4*)(Bp + (size_t)(t * 16 + bk + r * 8) * NPIX + bn);
    };
    auto sts = [&](int buf) {
        #pragma unroll
        for (int j = 0; j < 2; j++) {
            const float v[4] = { ra[j].x, ra[j].y, ra[j].z, ra[j].w };
            #pragma unroll
            for (int i = 0; i < 4; i++) {
                const int k = ak + j * 4 + i;
                As[buf][k][am ^ swz(k)] = to_tf32(v[i]);
            }
        }
        #pragma unroll
        for (int r = 0; r < 2; r++) {
            const int k = bk + r * 8;
            float4 v = rb[r];
            v.x = to_tf32(v.x); v.y = to_tf32(v.y);
            v.z = to_tf32(v.z); v.w = to_tf32(v.w);
            *(float4*)&Bs[buf][k][bn ^ swz(k)] = v;
        }
    };
    auto compute = [&](int buf) {
        #pragma unroll
        for (int ks = 0; ks < 2; ks++) {
            const int k0 = ks * 8 + tq, k1 = k0 + 4;
            const int g0 = swz(k0),     g1 = swz(k1);
            uint32_t af[4][4], bf[4][2];
            #pragma unroll
            for (int mf = 0; mf < 4; mf++) {
                const int m0 = wm * 64 + mf * 16 + gp;
                af[mf][0] = __float_as_uint(As[buf][k0][(m0    ) ^ g0]);
                af[mf][1] = __float_as_uint(As[buf][k0][(m0 + 8) ^ g0]);
                af[mf][2] = __float_as_uint(As[buf][k1][(m0    ) ^ g1]);
                af[mf][3] = __float_as_uint(As[buf][k1][(m0 + 8) ^ g1]);
            }
            #pragma unroll
            for (int nf = 0; nf < 4; nf++) {
                const int n0 = wn * 32 + nf * 8 + gp;
                bf[nf][0] = __float_as_uint(Bs[buf][k0][n0 ^ g0]);
                bf[nf][1] = __float_as_uint(Bs[buf][k1][n0 ^ g1]);
            }
            #pragma unroll
            for (int mf = 0; mf < 4; mf++)
                #pragma unroll
                for (int nf = 0; nf < 4; nf++)
                    mma_tf32(acc[mf][nf], af[mf], bf[nf]);
        }
    };

    constexpr int T = K / 16;
    ldg(0);
    sts(0);
    __syncthreads();
    #pragma unroll 1
    for (int t = 0; t < T; t++) {
        if (t + 1 < T) ldg(t + 1);
        compute(t & 1);
        if (t + 1 < T) {
            sts((t + 1) & 1);
            __syncthreads();
        }
    }

    // --- epilogue ---
    const int mg0 = mt * 128 + wm * 64;
    const int ng0 = bx * 128 + wn * 32;
    float* Cz = Cg + (size_t)z * M * NPIX;
    float lsum = 0.f, lsq = 0.f;

    #pragma unroll
    for (int mf = 0; mf < 4; mf++) {
        const int r0 = mg0 + mf * 16 + gp;
        const float bv0 = EPI ? bias[r0]     : 0.f;
        const float bv1 = EPI ? bias[r0 + 8] : 0.f;
        #pragma unroll
        for (int nf = 0; nf < 4; nf++) {
            const int c0 = ng0 + nf * 8 + tq * 2;
            float2 v0, v1;
            v0.x = acc[mf][nf][0] + bv0;
            v0.y = acc[mf][nf][1] + bv0;
            v1.x = acc[mf][nf][2] + bv1;
            v1.y = acc[mf][nf][3] + bv1;
            if (EPI) {
                lsum += v0.x + v0.y + v1.x + v1.y;
                lsq  += v0.x * v0.x + v0.y * v0.y + v1.x * v1.x + v1.y * v1.y;
            }
            *(float2*)&Cz[(size_t)r0       * NPIX + c0] = v0;
            *(float2*)&Cz[(size_t)(r0 + 8) * NPIX + c0] = v1;
        }
    }

    if (EPI) {
        __shared__ float rs[8], rq[8];
        #pragma unroll
        for (int o = 16; o; o >>= 1) {
            lsum += __shfl_xor_sync(0xffffffffu, lsum, o);
            lsq  += __shfl_xor_sync(0xffffffffu, lsq,  o);
        }
        if (lane == 0) { rs[wid] = lsum; rq[wid] = lsq; }
        __syncthreads();
        if (tid == 0) {
            float s = 0.f, q = 0.f;
            #pragma unroll
            for (int w = 0; w < 8; w++) { s += rs[w]; q += rq[w]; }
            atomicAdd(&g_stats[2 * z + 0], s);
            atomicAdd(&g_stats[2 * z + 1], q);
        }
    }
}

// ---------------------------------------------------------------------------
// K2: fused attention core. One block per (head, batch), 1024 threads.
// ---------------------------------------------------------------------------
__global__ __launch_bounds__(1024)
void k_attn()
{
    const int h = blockIdx.x, b = blockIdx.y;
    const int tid = threadIdx.x, lane = tid & 31, wid = tid >> 5;

    __shared__ float rowmax[32], rowinv[32];
    __shared__ float ks[32][128];
    __shared__ float vs[32][129];
    __shared__ float ctx[32][33];

    const float* qbase = g_qkv + ((size_t)b * O3 + 0 * HID + h * DH) * NPIX;
    const float* kbase = g_qkv + ((size_t)b * O3 + 1 * HID + h * DH) * NPIX;
    const float* vbase = g_qkv + ((size_t)b * O3 + 2 * HID + h * DH) * NPIX;

    {
        const float* kr = kbase + (size_t)wid * NPIX;
        float m = -1e30f;
        for (int n = lane; n < NPIX; n += 32) m = fmaxf(m, kr[n]);
        #pragma unroll
        for (int off = 16; off; off >>= 1)
            m = fmaxf(m, __shfl_xor_sync(0xffffffffu, m, off));
        float s = 0.f;
        for (int n = lane; n < NPIX; n += 32) s += __expf(kr[n] - m);
        #pragma unroll
        for (int off = 16; off; off >>= 1)
            s += __shfl_xor_sync(0xffffffffu, s, off);
        if (lane == 0) { rowmax[wid] = m; rowinv[wid] = 1.f / s; }
    }
    __syncthreads();

    const int d = wid, e = lane;
    float acc = 0.f;
    for (int nc = 0; nc < NPIX; nc += 128) {
        #pragma unroll
        for (int t = tid; t < 32 * 128; t += 1024) {
            const int dd = t >> 7, j = t & 127;
            const size_t off = (size_t)dd * NPIX + nc + j;
            ks[dd][j] = __expf(kbase[off] - rowmax[dd]) * rowinv[dd];
            vs[dd][j] = vbase[off];
        }
        __syncthreads();
        #pragma unroll
        for (int j = 0; j < 128; j++)
            acc += ks[d][j] * vs[e][j];
        __syncthreads();
    }
    ctx[d][e] = acc;
    __syncthreads();

    const float scale = 0.17677669529663687f;
    float* obase = g_attn + ((size_t)b * HID + h * DH) * NPIX;

    for (int n = tid; n < NPIX; n += 1024) {
        float q[32];
        float m = -1e30f;
        #pragma unroll
        for (int dd = 0; dd < 32; dd++) {
            q[dd] = qbase[(size_t)dd * NPIX + n];
            m = fmaxf(m, q[dd]);
        }
        float s = 0.f;
        #pragma unroll
        for (int dd = 0; dd < 32; dd++) { q[dd] = __expf(q[dd] - m); s += q[dd]; }
        const float inv = scale / s;
        #pragma unroll
        for (int dd = 0; dd < 32; dd++) q[dd] *= inv;

        #pragma unroll
        for (int ee = 0; ee < 32; ee++) {
            float o = 0.f;
            #pragma unroll
            for (int dd = 0; dd < 32; dd++) o += ctx[dd][ee] * q[dd];
            obase[(size_t)ee * NPIX + n] = o;
        }
    }
}

// ---------------------------------------------------------------------------
// K4: in-place GroupNorm (per-batch stats) + per-channel affine
// ---------------------------------------------------------------------------
__global__ __launch_bounds__(256)
void k_gn(float* __restrict__ out,
          const float* __restrict__ gn_w,
          const float* __restrict__ gn_b)
{
    const size_t gid  = (size_t)blockIdx.x * blockDim.x + threadIdx.x;
    const size_t base = gid * 4;
    const int b = (int)(base >> 20);
    const int c = (int)((base >> 12) & 255);

    const float invN = 1.f / (256.f * 4096.f);
    const float mean = g_stats[2 * b + 0] * invN;
    const float var  = g_stats[2 * b + 1] * invN - mean * mean;
    const float r    = rsqrtf(var + EPS);
    const float w    = gn_w[c] * r;
    const float bb   = gn_b[c] - mean * w;

    float4 v = *(float4*)&out[base];
    v.x = v.x * w + bb;
    v.y = v.y * w + bb;
    v.z = v.z * w + bb;
    v.w = v.w * w + bb;
    *(float4*)&out[base] = v;
}

// ---------------------------------------------------------------------------
// Launch
// ---------------------------------------------------------------------------
extern "C" void kernel_launch(void* const* d_in, const int* in_sizes, int n_in,
                              void* d_out, int out_size)
{
    const float* x     = (const float*)d_in[0];
    const float* w_qkv = (const float*)d_in[1];
    const float* w_out = (const float*)d_in[2];
    const float* b_out = (const float*)d_in[3];
    const float* gn_w  = (const float*)d_in[4];
    const float* gn_b  = (const float*)d_in[5];
    float* out = (float*)d_out;

    float *p_qkv, *p_attn;
    cudaGetSymbolAddress((void**)&p_qkv,  g_qkv);
    cudaGetSymbolAddress((void**)&p_attn, g_attn);

    // K0: zero stats
    k_zero_stats<<<1, 64>>>();

    // K1: QKV projection  [384,256] x [256,4096] per batch (tf32 HMMA)
    k_mma<CIN, O3, false>
        <<<dim3(NPIX / 128, O3 / 128, BATCH), 256>>>(w_qkv, x, p_qkv, nullptr);

    // K2: attention core
    k_attn<<<dim3(HEADS, BATCH), 1024>>>();

    // K3: output projection + bias + stats  [256,128] x [128,4096] per batch
    k_mma<HID, CIN, true>
        <<<dim3(NPIX / 128, CIN / 128, BATCH), 256>>>(w_out, p_attn, out, b_out);

    // K4: GroupNorm normalize in place
    k_gn<<<(BATCH * CIN * NPIX / 4) / 256, 256>>>(out, gn_w, gn_b);
}

// round 6
// speedup vs baseline: 1.3276x; 1.0230x over previous
#include <cuda_runtime.h>
#include <cstdint>

// Problem constants
#define BATCH   32
#define CIN     256
#define NPIX    4096          // 64*64
#define HEADS   4
#define DH      32
#define HID     128           // HEADS*DH
#define O3      384           // 3*HID
#define EPS     1e-5f

// ---------------------------------------------------------------------------
// Scratch (device globals: allocation-free)
// ---------------------------------------------------------------------------
__device__ float g_qkv [(size_t)BATCH * O3  * NPIX];   // 201 MB
__device__ float g_attn[(size_t)BATCH * HID * NPIX];   //  67 MB
__device__ float g_stats[BATCH * 2];                   // sum, sumsq per batch
__device__ float g_kmax [BATCH * HEADS * 32];
__device__ float g_kinv [BATCH * HEADS * 32];
__device__ float g_ctx  [BATCH * HEADS * 32 * 32];     // 512 KB

// ---------------------------------------------------------------------------
// K0: zero the accumulators (stats + ctx)
// ---------------------------------------------------------------------------
#define ZERO_N (BATCH * HEADS * 32 * 32 + BATCH * 2)
__global__ void k_zero() {
    const int i = blockIdx.x * blockDim.x + threadIdx.x;
    if (i < BATCH * HEADS * 32 * 32) g_ctx[i] = 0.f;
    else if (i < ZERO_N) g_stats[i - BATCH * HEADS * 32 * 32] = 0.f;
}

// ---------------------------------------------------------------------------
// helpers (all sm_80-baseline PTX: compiles at compute_103)
// ---------------------------------------------------------------------------
__device__ __forceinline__ float to_tf32(float x) {
    uint32_t u;
    asm("cvt.rna.tf32.f32 %0, %1;" : "=r"(u) : "f"(x));
    return __uint_as_float(u);
}
__device__ __forceinline__ void mma_tf32(float c[4],
                                         const uint32_t a[4],
                                         const uint32_t b[2]) {
    asm volatile(
        "mma.sync.aligned.m16n8k8.row.col.f32.tf32.tf32.f32 "
        "{%0,%1,%2,%3}, {%4,%5,%6,%7}, {%8,%9}, {%0,%1,%2,%3};"
        : "+f"(c[0]), "+f"(c[1]), "+f"(c[2]), "+f"(c[3])
        : "r"(a[0]), "r"(a[1]), "r"(a[2]), "r"(a[3]),
          "r"(b[0]), "r"(b[1]));
}
__device__ __forceinline__ void cpasync16(uint32_t s, const void* g) {
    asm volatile("cp.async.cg.shared.global [%0], [%1], 16;"
                 :: "r"(s), "l"(g) : "memory");
}
#define CP_COMMIT() asm volatile("cp.async.commit_group;" ::: "memory")
#define CP_WAIT2()  asm volatile("cp.async.wait_group 2;"  ::: "memory")

// smem column swizzle: conflict-free for both staging STS/cp.async and
// fragment LDS (k = lane&3 rows, m/n = lane>>2 cols).
__device__ __forceinline__ int swz(int k) {
    return (((k & 3) ^ ((k >> 2) & 3)) << 3);   // {0,8,16,24}
}

// ---------------------------------------------------------------------------
// tf32 tensor-core GEMM:  C[z][M][4096] = A[M,K] * B[z][K,4096]  (+bias,+stats)
// CTA tile 128x128, BK=16, 8 warps (2m x 4n), warp tile 64x32.
// B: cp.async 4-stage ring (prefetch distance 3), raw fp32, cvt post-LDS.
// A: LDG->cvt->STS, 4 buffers, prefetch distance 3 (A is L2-hot weights).
// ---------------------------------------------------------------------------
#define MMA_SMEM (4 * 16 * 128 * 4 * 2)   // 64 KB dynamic

template<int K, int M, bool EPI>
__global__ __launch_bounds__(256, 2)
void k_mma(const float* __restrict__ A, const float* __restrict__ Bg,
           float* __restrict__ Cg, const float* __restrict__ bias)
{
    extern __shared__ float sm[];
    float (*As)[16][128] = (float (*)[16][128])sm;                 // 4 stages
    float (*Bs)[16][128] = (float (*)[16][128])(sm + 4 * 16 * 128);

    const int tid  = threadIdx.x, lane = tid & 31, wid = tid >> 5;
    const int wm   = wid >> 2, wn = wid & 3;
    const int tq   = lane & 3, gp = lane >> 2;
    const int bx   = blockIdx.x, mt = blockIdx.y, z = blockIdx.z;

    const float* Ap = A  + (size_t)mt * 128 * K;
    const float* Bp = Bg + (size_t)z * K * NPIX + bx * 128;

    // A loader: row am, col base ak (2 float4)
    const int am = tid & 127, ak = (tid >> 7) * 8;
    // B loader: row bkr (0..15), col bc (0..120, 8 floats via 2 cp.async)
    const int bkr = tid >> 4;
    const int bc  = (tid & 15) * 8;
    const uint32_t bsw = (uint32_t)(bc ^ swz(bkr));
    const uint32_t bs_base =
        (uint32_t)__cvta_generic_to_shared(&Bs[0][0][0]) + (bkr * 128 + bsw) * 4;

    float acc[4][4][4];
    #pragma unroll
    for (int i = 0; i < 4; i++)
        #pragma unroll
        for (int j = 0; j < 4; j++)
            #pragma unroll
            for (int r = 0; r < 4; r++) acc[i][j][r] = 0.f;

    auto ldgstsA = [&](int t) {
        const int buf = t & 3;
        #pragma unroll
        for (int j = 0; j < 2; j++) {
            float4 v = *(const float4*)(Ap + (size_t)am * K + t * 16 + ak + j * 4);
            const float e[4] = { v.x, v.y, v.z, v.w };
            #pragma unroll
            for (int i = 0; i < 4; i++) {
                const int k = ak + j * 4 + i;
                As[buf][k][am ^ swz(k)] = to_tf32(e[i]);
            }
        }
    };
    auto cpB = [&](int t) {
        const float* src = Bp + (size_t)(t * 16 + bkr) * NPIX + bc;
        const uint32_t dst = bs_base + (uint32_t)((t & 3) * 16 * 128 * 4);
        cpasync16(dst,      src);
        cpasync16(dst + 16, src + 4);
    };
    auto compute = [&](int t) {
        const int buf = t & 3;
        #pragma unroll
        for (int ks = 0; ks < 2; ks++) {
            const int k0 = ks * 8 + tq, k1 = k0 + 4;
            const int g0 = swz(k0),     g1 = swz(k1);
            uint32_t af[4][4], bf[4][2];
            #pragma unroll
            for (int mf = 0; mf < 4; mf++) {
                const int m0 = wm * 64 + mf * 16 + gp;
                af[mf][0] = __float_as_uint(As[buf][k0][(m0    ) ^ g0]);
                af[mf][1] = __float_as_uint(As[buf][k0][(m0 + 8) ^ g0]);
                af[mf][2] = __float_as_uint(As[buf][k1][(m0    ) ^ g1]);
                af[mf][3] = __float_as_uint(As[buf][k1][(m0 + 8) ^ g1]);
            }
            #pragma unroll
            for (int nf = 0; nf < 4; nf++) {
                const int n0 = wn * 32 + nf * 8 + gp;
                bf[nf][0] = __float_as_uint(to_tf32(Bs[buf][k0][n0 ^ g0]));
                bf[nf][1] = __float_as_uint(to_tf32(Bs[buf][k1][n0 ^ g1]));
            }
            #pragma unroll
            for (int mf = 0; mf < 4; mf++)
                #pragma unroll
                for (int nf = 0; nf < 4; nf++)
                    mma_tf32(acc[mf][nf], af[mf], bf[nf]);
        }
    };

    constexpr int T = K / 16;   // >= 8

    // prologue: stages 0..2 in flight
    #pragma unroll
    for (int s = 0; s < 3; s++) {
        cpB(s);
        CP_COMMIT();
        ldgstsA(s);
    }

    #pragma unroll 4
    for (int t = 0; t < T; t++) {
        CP_WAIT2();          // committed groups: 3+t, allow 2 pending -> stage t done
        __syncthreads();     // all threads' waits done; As[t&3] visible
        compute(t);
        if (t + 3 < T) {
            cpB(t + 3);
            ldgstsA(t + 3);  // buffer (t+3)&3: last read compute(t-1), pre-barrier. safe.
        }
        CP_COMMIT();         // always commit (empty group keeps wait counting valid)
    }

    // --- epilogue ---
    const int mg0 = mt * 128 + wm * 64;
    const int ng0 = bx * 128 + wn * 32;
    float* Cz = Cg + (size_t)z * M * NPIX;
    float lsum = 0.f, lsq = 0.f;

    #pragma unroll
    for (int mf = 0; mf < 4; mf++) {
        const int r0 = mg0 + mf * 16 + gp;
        const float bv0 = EPI ? bias[r0]     : 0.f;
        const float bv1 = EPI ? bias[r0 + 8] : 0.f;
        #pragma unroll
        for (int nf = 0; nf < 4; nf++) {
            const int c0 = ng0 + nf * 8 + tq * 2;
            float2 v0, v1;
            v0.x = acc[mf][nf][0] + bv0;
            v0.y = acc[mf][nf][1] + bv0;
            v1.x = acc[mf][nf][2] + bv1;
            v1.y = acc[mf][nf][3] + bv1;
            if (EPI) {
                lsum += v0.x + v0.y + v1.x + v1.y;
                lsq  += v0.x * v0.x + v0.y * v0.y + v1.x * v1.x + v1.y * v1.y;
            }
            *(float2*)&Cz[(size_t)r0       * NPIX + c0] = v0;
            *(float2*)&Cz[(size_t)(r0 + 8) * NPIX + c0] = v1;
        }
    }

    if (EPI) {
        __shared__ float rs[8], rq[8];
        #pragma unroll
        for (int o = 16; o; o >>= 1) {
            lsum += __shfl_xor_sync(0xffffffffu, lsum, o);
            lsq  += __shfl_xor_sync(0xffffffffu, lsq,  o);
        }
        if (lane == 0) { rs[wid] = lsum; rq[wid] = lsq; }
        __syncthreads();
        if (tid == 0) {
            float s = 0.f, q = 0.f;
            #pragma unroll
            for (int w = 0; w < 8; w++) { s += rs[w]; q += rq[w]; }
            atomicAdd(&g_stats[2 * z + 0], s);
            atomicAdd(&g_stats[2 * z + 1], q);
        }
    }
}

// ---------------------------------------------------------------------------
// K2a: k-softmax stats. One block per (h,b), warp wid owns row d=wid.
// ---------------------------------------------------------------------------
__global__ __launch_bounds__(1024)
void k_kstats()
{
    const int h = blockIdx.x, b = blockIdx.y;
    const int lane = threadIdx.x & 31, wid = threadIdx.x >> 5;
    const float* kr = g_qkv + ((size_t)b * O3 + HID + h * DH + wid) * NPIX;

    float m = -1e30f;
    for (int n = lane; n < NPIX; n += 32) m = fmaxf(m, kr[n]);
    #pragma unroll
    for (int off = 16; off; off >>= 1)
        m = fmaxf(m, __shfl_xor_sync(0xffffffffu, m, off));
    float s = 0.f;
    for (int n = lane; n < NPIX; n += 32) s += __expf(kr[n] - m);
    #pragma unroll
    for (int off = 16; off; off >>= 1)
        s += __shfl_xor_sync(0xffffffffu, s, off);
    if (lane == 0) {
        g_kmax[(b * HEADS + h) * 32 + wid] = m;
        g_kinv[(b * HEADS + h) * 32 + wid] = 1.f / s;
    }
}

// ---------------------------------------------------------------------------
// K2b: context partials. Block (chunk, h, b) covers 512 n-cols; thread (d,e)
// accumulates ctx[d][e] partial, atomicAdd into g_ctx.
// ---------------------------------------------------------------------------
__global__ __launch_bounds__(1024)
void k_ctx()
{
    const int ch = blockIdx.x, h = blockIdx.y, b = blockIdx.z;
    const int tid = threadIdx.x, lane = tid & 31, wid = tid >> 5;

    __shared__ float rowmax[32], rowinv[32];
    __shared__ float ks[32][128];
    __shared__ float vs[32][129];

    const float* kbase = g_qkv + ((size_t)b * O3 + HID     + h * DH) * NPIX;
    const float* vbase = g_qkv + ((size_t)b * O3 + 2 * HID + h * DH) * NPIX;

    if (tid < 32) {
        rowmax[tid] = g_kmax[(b * HEADS + h) * 32 + tid];
        rowinv[tid] = g_kinv[(b * HEADS + h) * 32 + tid];
    }
    __syncthreads();

    const int d = wid, e = lane;
    const int n0 = ch * 512;
    float acc = 0.f;
    for (int nc = n0; nc < n0 + 512; nc += 128) {
        #pragma unroll
        for (int t = tid; t < 32 * 128; t += 1024) {
            const int dd = t >> 7, j = t & 127;
            const size_t off = (size_t)dd * NPIX + nc + j;
            ks[dd][j] = __expf(kbase[off] - rowmax[dd]) * rowinv[dd];
            vs[dd][j] = vbase[off];
        }
        __syncthreads();
        #pragma unroll
        for (int j = 0; j < 128; j++)
            acc += ks[d][j] * vs[e][j];
        __syncthreads();
    }
    atomicAdd(&g_ctx[((b * HEADS + h) * 32 + d) * 32 + e], acc);
}

// ---------------------------------------------------------------------------
// K2c: q softmax + out = ctx^T q.  Block (chunk, h, b) covers 1024 n-cols.
// ---------------------------------------------------------------------------
__global__ __launch_bounds__(256)
void k_qout()
{
    const int ch = blockIdx.x, h = blockIdx.y, b = blockIdx.z;
    const int tid = threadIdx.x;

    __shared__ float ctx[32][32];
    #pragma unroll
    for (int i = tid; i < 1024; i += 256)
        ctx[i >> 5][i & 31] = g_ctx[(b * HEADS + h) * 1024 + i];
    __syncthreads();

    const float* qbase = g_qkv  + ((size_t)b * O3  + h * DH) * NPIX;
    float*       obase = g_attn + ((size_t)b * HID + h * DH) * NPIX;
    const float scale = 0.17677669529663687f;   // 32^-0.5

    #pragma unroll 1
    for (int i = 0; i < 4; i++) {
        const int n = ch * 1024 + i * 256 + tid;
        float q[32];
        float m = -1e30f;
        #pragma unroll
        for (int dd = 0; dd < 32; dd++) {
            q[dd] = qbase[(size_t)dd * NPIX + n];
            m = fmaxf(m, q[dd]);
        }
        float s = 0.f;
        #pragma unroll
        for (int dd = 0; dd < 32; dd++) { q[dd] = __expf(q[dd] - m); s += q[dd]; }
        const float inv = scale / s;
        #pragma unroll
        for (int dd = 0; dd < 32; dd++) q[dd] *= inv;

        #pragma unroll
        for (int ee = 0; ee < 32; ee++) {
            float o = 0.f;
            #pragma unroll
            for (int dd = 0; dd < 32; dd++) o += ctx[dd][ee] * q[dd];
            obase[(size_t)ee * NPIX + n] = o;
        }
    }
}

// ---------------------------------------------------------------------------
// K4: in-place GroupNorm (per-batch stats) + per-channel affine
// ---------------------------------------------------------------------------
__global__ __launch_bounds__(256)
void k_gn(float* __restrict__ out,
          const float* __restrict__ gn_w,
          const float* __restrict__ gn_b)
{
    const size_t gid  = (size_t)blockIdx.x * blockDim.x + threadIdx.x;
    const size_t base = gid * 4;
    const int b = (int)(base >> 20);
    const int c = (int)((base >> 12) & 255);

    const float invN = 1.f / (256.f * 4096.f);
    const float mean = g_stats[2 * b + 0] * invN;
    const float var  = g_stats[2 * b + 1] * invN - mean * mean;
    const float r    = rsqrtf(var + EPS);
    const float w    = gn_w[c] * r;
    const float bb   = gn_b[c] - mean * w;

    float4 v = *(float4*)&out[base];
    v.x = v.x * w + bb;
    v.y = v.y * w + bb;
    v.z = v.z * w + bb;
    v.w = v.w * w + bb;
    *(float4*)&out[base] = v;
}

// ---------------------------------------------------------------------------
// Launch
// ---------------------------------------------------------------------------
extern "C" void kernel_launch(void* const* d_in, const int* in_sizes, int n_in,
                              void* d_out, int out_size)
{
    const float* x     = (const float*)d_in[0];
    const float* w_qkv = (const float*)d_in[1];
    const float* w_out = (const float*)d_in[2];
    const float* b_out = (const float*)d_in[3];
    const float* gn_w  = (const float*)d_in[4];
    const float* gn_b  = (const float*)d_in[5];
    float* out = (float*)d_out;

    float *p_qkv, *p_attn;
    cudaGetSymbolAddress((void**)&p_qkv,  g_qkv);
    cudaGetSymbolAddress((void**)&p_attn, g_attn);

    cudaFuncSetAttribute(k_mma<CIN, O3, false>,
                         cudaFuncAttributeMaxDynamicSharedMemorySize, MMA_SMEM);
    cudaFuncSetAttribute(k_mma<HID, CIN, true>,
                         cudaFuncAttributeMaxDynamicSharedMemorySize, MMA_SMEM);

    // K0: zero stats + ctx
    k_zero<<<(ZERO_N + 255) / 256, 256>>>();

    // K1: QKV projection  [384,256] x [256,4096] per batch (tf32 HMMA, cp.async)
    k_mma<CIN, O3, false>
        <<<dim3(NPIX / 128, O3 / 128, BATCH), 256, MMA_SMEM>>>(w_qkv, x, p_qkv, nullptr);

    // K2: attention core, split for parallelism
    k_kstats<<<dim3(HEADS, BATCH), 1024>>>();
    k_ctx   <<<dim3(8, HEADS, BATCH), 1024>>>();
    k_qout  <<<dim3(4, HEADS, BATCH), 256>>>();

    // K3: output projection + bias + stats  [256,128] x [128,4096] per batch
    k_mma<HID, CIN, true>
        <<<dim3(NPIX / 128, CIN / 128, BATCH), 256, MMA_SMEM>>>(w_out, p_attn, out, b_out);

    // K4: GroupNorm normalize in place
    k_gn<<<(BATCH * CIN * NPIX / 4) / 256, 256>>>(out, gn_w, gn_b);
}

// round 7
// speedup vs baseline: 1.4342x; 1.0804x over previous
#include <cuda_runtime.h>
#include <cstdint>

// Problem constants
#define BATCH   32
#define CIN     256
#define NPIX    4096          // 64*64
#define HEADS   4
#define DH      32
#define HID     128           // HEADS*DH
#define O3      384           // 3*HID
#define EPS     1e-5f

// ---------------------------------------------------------------------------
// Scratch (device globals: allocation-free)
// ---------------------------------------------------------------------------
__device__ float g_qkv [(size_t)BATCH * O3  * NPIX];   // 201 MB
__device__ float g_attn[(size_t)BATCH * HID * NPIX];   //  67 MB
__device__ float g_stats[BATCH * 2];                   // sum, sumsq per batch
__device__ float g_kmax [BATCH * HEADS * 32];
__device__ float g_kinv [BATCH * HEADS * 32];
__device__ float g_ctx  [BATCH * HEADS * 32 * 32];     // 512 KB

// ---------------------------------------------------------------------------
// K0: zero the accumulators (stats + ctx)
// ---------------------------------------------------------------------------
#define ZERO_N (BATCH * HEADS * 32 * 32 + BATCH * 2)
__global__ void k_zero() {
    const int i = blockIdx.x * blockDim.x + threadIdx.x;
    if (i < BATCH * HEADS * 32 * 32) g_ctx[i] = 0.f;
    else if (i < ZERO_N) g_stats[i - BATCH * HEADS * 32 * 32] = 0.f;
}

// ---------------------------------------------------------------------------
// helpers (all sm_80-baseline PTX: compiles at compute_103)
// ---------------------------------------------------------------------------
__device__ __forceinline__ float to_tf32(float x) {
    uint32_t u;
    asm("cvt.rna.tf32.f32 %0, %1;" : "=r"(u) : "f"(x));
    return __uint_as_float(u);
}
__device__ __forceinline__ void mma_tf32(float c[4],
                                         const uint32_t a[4],
                                         const uint32_t b[2]) {
    asm volatile(
        "mma.sync.aligned.m16n8k8.row.col.f32.tf32.tf32.f32 "
        "{%0,%1,%2,%3}, {%4,%5,%6,%7}, {%8,%9}, {%0,%1,%2,%3};"
        : "+f"(c[0]), "+f"(c[1]), "+f"(c[2]), "+f"(c[3])
        : "r"(a[0]), "r"(a[1]), "r"(a[2]), "r"(a[3]),
          "r"(b[0]), "r"(b[1]));
}
__device__ __forceinline__ void cpasync16(uint32_t s, const void* g) {
    asm volatile("cp.async.cg.shared.global [%0], [%1], 16;"
                 :: "r"(s), "l"(g) : "memory");
}
#define CP_COMMIT() asm volatile("cp.async.commit_group;" ::: "memory")
#define CP_WAIT2()  asm volatile("cp.async.wait_group 2;"  ::: "memory")

// smem column swizzle: conflict-free for staging and fragment access.
__device__ __forceinline__ int swz(int k) {
    return (((k & 3) ^ ((k >> 2) & 3)) << 3);   // {0,8,16,24}
}

// ---------------------------------------------------------------------------
// tf32 tensor-core GEMM:  C[z][M][4096] = A[M,K] * B[z][K,4096]  (+bias,+stats)
// CTA tile 128x128, BK=16, 8 warps (2m x 4n), warp tile 64x32.
// B: cp.async 4-stage ring (distance 3). A: LDG dist-2 regs, STS dist-1,
// double-buffered smem.
// ---------------------------------------------------------------------------
#define MMA_SMEM ((2 + 4) * 16 * 128 * 4)   // A 2 stages + B 4 stages = 48 KB

template<int K, int M, bool EPI>
__global__ __launch_bounds__(256)
void k_mma(const float* __restrict__ A, const float* __restrict__ Bg,
           float* __restrict__ Cg, const float* __restrict__ bias)
{
    extern __shared__ float sm[];
    float (*As)[16][128] = (float (*)[16][128])sm;                 // 2 stages
    float (*Bs)[16][128] = (float (*)[16][128])(sm + 2 * 16 * 128);// 4 stages

    const int tid  = threadIdx.x, lane = tid & 31, wid = tid >> 5;
    const int wm   = wid >> 2, wn = wid & 3;
    const int tq   = lane & 3, gp = lane >> 2;
    const int bx   = blockIdx.x, mt = blockIdx.y, z = blockIdx.z;

    const float* Ap = A  + (size_t)mt * 128 * K;
    const float* Bp = Bg + (size_t)z * K * NPIX + bx * 128;

    // A loader: row am, col base ak (2 float4)
    const int am = tid & 127, ak = (tid >> 7) * 8;
    // B loader: row bkr (0..15), col bc (2 cp.async of 16B)
    const int bkr = tid >> 4;
    const int bc  = (tid & 15) * 8;
    const uint32_t bsw = (uint32_t)(bc ^ swz(bkr));
    const uint32_t bs_base =
        (uint32_t)__cvta_generic_to_shared(&Bs[0][0][0]) + (bkr * 128 + bsw) * 4;

    float acc[4][4][4];
    #pragma unroll
    for (int i = 0; i < 4; i++)
        #pragma unroll
        for (int j = 0; j < 4; j++)
            #pragma unroll
            for (int r = 0; r < 4; r++) acc[i][j][r] = 0.f;

    float4 ra[2];
    auto ldgA = [&](int t) {
        #pragma unroll
        for (int j = 0; j < 2; j++)
            ra[j] = *(const float4*)(Ap + (size_t)am * K + t * 16 + ak + j * 4);
    };
    auto stsA = [&](int t) {
        const int buf = t & 1;
        #pragma unroll
        for (int j = 0; j < 2; j++) {
            const float e[4] = { ra[j].x, ra[j].y, ra[j].z, ra[j].w };
            #pragma unroll
            for (int i = 0; i < 4; i++) {
                const int k = ak + j * 4 + i;
                As[buf][k][am ^ swz(k)] = to_tf32(e[i]);
            }
        }
    };
    auto cpB = [&](int t) {
        const float* src = Bp + (size_t)(t * 16 + bkr) * NPIX + bc;
        const uint32_t dst = bs_base + (uint32_t)((t & 3) * 16 * 128 * 4);
        cpasync16(dst,      src);
        cpasync16(dst + 16, src + 4);
    };
    auto compute = [&](int t) {
        const int abuf = t & 1, bbuf = t & 3;
        #pragma unroll
        for (int ks = 0; ks < 2; ks++) {
            const int k0 = ks * 8 + tq, k1 = k0 + 4;
            const int g0 = swz(k0),     g1 = swz(k1);
            uint32_t af[4][4], bf[4][2];
            #pragma unroll
            for (int mf = 0; mf < 4; mf++) {
                const int m0 = wm * 64 + mf * 16 + gp;
                af[mf][0] = __float_as_uint(As[abuf][k0][(m0    ) ^ g0]);
                af[mf][1] = __float_as_uint(As[abuf][k0][(m0 + 8) ^ g0]);
                af[mf][2] = __float_as_uint(As[abuf][k1][(m0    ) ^ g1]);
                af[mf][3] = __float_as_uint(As[abuf][k1][(m0 + 8) ^ g1]);
            }
            #pragma unroll
            for (int nf = 0; nf < 4; nf++) {
                const int n0 = wn * 32 + nf * 8 + gp;
                bf[nf][0] = __float_as_uint(to_tf32(Bs[bbuf][k0][n0 ^ g0]));
                bf[nf][1] = __float_as_uint(to_tf32(Bs[bbuf][k1][n0 ^ g1]));
            }
            #pragma unroll
            for (int mf = 0; mf < 4; mf++)
                #pragma unroll
                for (int nf = 0; nf < 4; nf++)
                    mma_tf32(acc[mf][nf], af[mf], bf[nf]);
        }
    };

    constexpr int T = K / 16;   // >= 8

    // prologue: B stages 0..2 in flight; A stage 0 stored, stage 1 in regs
    ldgA(0);
    cpB(0); CP_COMMIT();
    cpB(1); CP_COMMIT();
    cpB(2); CP_COMMIT();
    stsA(0);
    ldgA(1);

    #pragma unroll 4
    for (int t = 0; t < T; t++) {
        CP_WAIT2();          // B stage t complete (commits = 3 + t)
        __syncthreads();     // As[t&1] from prev iter + Bs[t&3] visible
        compute(t);
        if (t + 1 < T) stsA(t + 1);   // consume ra -> As[(t+1)&1]
        if (t + 2 < T) ldgA(t + 2);   // refill ra (L2-hot weights)
        if (t + 3 < T) cpB(t + 3);
        CP_COMMIT();         // empty commits in tail keep wait counting valid
    }

    // --- epilogue ---
    const int mg0 = mt * 128 + wm * 64;
    const int ng0 = bx * 128 + wn * 32;
    float* Cz = Cg + (size_t)z * M * NPIX;
    float lsum = 0.f, lsq = 0.f;

    #pragma unroll
    for (int mf = 0; mf < 4; mf++) {
        const int r0 = mg0 + mf * 16 + gp;
        const float bv0 = EPI ? bias[r0]     : 0.f;
        const float bv1 = EPI ? bias[r0 + 8] : 0.f;
        #pragma unroll
        for (int nf = 0; nf < 4; nf++) {
            const int c0 = ng0 + nf * 8 + tq * 2;
            float2 v0, v1;
            v0.x = acc[mf][nf][0] + bv0;
            v0.y = acc[mf][nf][1] + bv0;
            v1.x = acc[mf][nf][2] + bv1;
            v1.y = acc[mf][nf][3] + bv1;
            if (EPI) {
                lsum += v0.x + v0.y + v1.x + v1.y;
                lsq  += v0.x * v0.x + v0.y * v0.y + v1.x * v1.x + v1.y * v1.y;
            }
            *(float2*)&Cz[(size_t)r0       * NPIX + c0] = v0;
            *(float2*)&Cz[(size_t)(r0 + 8) * NPIX + c0] = v1;
        }
    }

    if (EPI) {
        __shared__ float rs[8], rq[8];
        #pragma unroll
        for (int o = 16; o; o >>= 1) {
            lsum += __shfl_xor_sync(0xffffffffu, lsum, o);
            lsq  += __shfl_xor_sync(0xffffffffu, lsq,  o);
        }
        if (lane == 0) { rs[wid] = lsum; rq[wid] = lsq; }
        __syncthreads();
        if (tid == 0) {
            float s = 0.f, q = 0.f;
            #pragma unroll
            for (int w = 0; w < 8; w++) { s += rs[w]; q += rq[w]; }
            atomicAdd(&g_stats[2 * z + 0], s);
            atomicAdd(&g_stats[2 * z + 1], q);
        }
    }
}

// ---------------------------------------------------------------------------
// K2a: k-softmax stats. One block per (h,b), warp wid owns row d=wid.
// ---------------------------------------------------------------------------
__global__ __launch_bounds__(1024)
void k_kstats()
{
    const int h = blockIdx.x, b = blockIdx.y;
    const int lane = threadIdx.x & 31, wid = threadIdx.x >> 5;
    const float4* kr = (const float4*)
        (g_qkv + ((size_t)b * O3 + HID + h * DH + wid) * NPIX);

    float m = -1e30f;
    #pragma unroll 4
    for (int n = lane; n < NPIX / 4; n += 32) {
        float4 v = kr[n];
        m = fmaxf(m, fmaxf(fmaxf(v.x, v.y), fmaxf(v.z, v.w)));
    }
    #pragma unroll
    for (int off = 16; off; off >>= 1)
        m = fmaxf(m, __shfl_xor_sync(0xffffffffu, m, off));
    float s = 0.f;
    #pragma unroll 4
    for (int n = lane; n < NPIX / 4; n += 32) {
        float4 v = kr[n];
        s += __expf(v.x - m) + __expf(v.y - m) + __expf(v.z - m) + __expf(v.w - m);
    }
    #pragma unroll
    for (int off = 16; off; off >>= 1)
        s += __shfl_xor_sync(0xffffffffu, s, off);
    if (lane == 0) {
        g_kmax[(b * HEADS + h) * 32 + wid] = m;
        g_kinv[(b * HEADS + h) * 32 + wid] = 1.f / s;
    }
}

// ---------------------------------------------------------------------------
// K2b: context partials, register-tiled. Block (chunk, h, b) covers 512 cols.
// 16 groups of 16 threads share a staged 32x64 tile; each thread owns an
// 8x8 ctx sub-tile accumulated over its group's j-subset; smem tree reduce.
// ---------------------------------------------------------------------------
#define CTX_SMEM (8192 * 4)   // 32 KB: max(staging 2*32*65=4160, red 8192) floats

__global__ __launch_bounds__(256)
void k_ctx()
{
    extern __shared__ float sm[];
    float* ks = sm;                 // [32][65]
    float* vs = sm + 32 * 65;       // [32][65]
    __shared__ float rowmax[32], rowinv[32];

    const int ch = blockIdx.x, h = blockIdx.y, b = blockIdx.z;
    const int tid = threadIdx.x;
    const int g = tid >> 4, t16 = tid & 15;
    const int d0 = (t16 >> 2) * 8, e0 = (t16 & 3) * 8;
    const int bh = b * HEADS + h;

    if (tid < 32) {
        rowmax[tid] = g_kmax[bh * 32 + tid];
        rowinv[tid] = g_kinv[bh * 32 + tid];
    }

    const float* kbase = g_qkv + ((size_t)b * O3 + HID     + h * DH) * NPIX;
    const float* vbase = g_qkv + ((size_t)b * O3 + 2 * HID + h * DH) * NPIX;

    const int r = tid >> 3, c0 = (tid & 7) * 8;   // staging map

    float acc[8][8];
    #pragma unroll
    for (int i = 0; i < 8; i++)
        #pragma unroll
        for (int j = 0; j < 8; j++) acc[i][j] = 0.f;

    __syncthreads();

    #pragma unroll 1
    for (int tile = 0; tile < 8; ++tile) {
        const int nc = ch * 512 + tile * 64;
        const float4 k0 = *(const float4*)(kbase + (size_t)r * NPIX + nc + c0);
        const float4 k1 = *(const float4*)(kbase + (size_t)r * NPIX + nc + c0 + 4);
        const float4 v0 = *(const float4*)(vbase + (size_t)r * NPIX + nc + c0);
        const float4 v1 = *(const float4*)(vbase + (size_t)r * NPIX + nc + c0 + 4);
        const float m = rowmax[r], iv = rowinv[r];
        float* kd = ks + r * 65 + c0;
        float* vd = vs + r * 65 + c0;
        kd[0] = __expf(k0.x - m) * iv; kd[1] = __expf(k0.y - m) * iv;
        kd[2] = __expf(k0.z - m) * iv; kd[3] = __expf(k0.w - m) * iv;
        kd[4] = __expf(k1.x - m) * iv; kd[5] = __expf(k1.y - m) * iv;
        kd[6] = __expf(k1.z - m) * iv; kd[7] = __expf(k1.w - m) * iv;
        vd[0] = v0.x; vd[1] = v0.y; vd[2] = v0.z; vd[3] = v0.w;
        vd[4] = v1.x; vd[5] = v1.y; vd[6] = v1.z; vd[7] = v1.w;
        __syncthreads();

        #pragma unroll
        for (int s = 0; s < 4; ++s) {
            const int j = g + s * 16;
            float ka[8], va[8];
            #pragma unroll
            for (int i = 0; i < 8; ++i) ka[i] = ks[(d0 + i) * 65 + j];
            #pragma unroll
            for (int i = 0; i < 8; ++i) va[i] = vs[(e0 + i) * 65 + j];
            #pragma unroll
            for (int i = 0; i < 8; ++i)
                #pragma unroll
                for (int jj = 0; jj < 8; ++jj)
                    acc[i][jj] += ka[i] * va[jj];
        }
        __syncthreads();
    }

    // tree reduction over the 16 groups (red aliases staging region)
    float* red = sm;
    #pragma unroll
    for (int step = 8; step >= 1; step >>= 1) {
        if (g >= step && g < 2 * step) {
            float* dst = red + ((g - step) * 16 + t16) * 64;
            #pragma unroll
            for (int q = 0; q < 64; ++q) dst[q] = acc[q >> 3][q & 7];
        }
        __syncthreads();
        if (g < step) {
            const float* src = red + (g * 16 + t16) * 64;
            #pragma unroll
            for (int q = 0; q < 64; ++q) acc[q >> 3][q & 7] += src[q];
        }
        __syncthreads();
    }
    if (g == 0) {
        float* dst = g_ctx + bh * 1024;
        #pragma unroll
        for (int i = 0; i < 8; ++i)
            #pragma unroll
            for (int jj = 0; jj < 8; ++jj)
                atomicAdd(&dst[(d0 + i) * 32 + (e0 + jj)], acc[i][jj]);
    }
}

// ---------------------------------------------------------------------------
// K2c: q softmax + out = ctx^T q.  Block (chunk, h, b) covers 1024 n-cols.
// ---------------------------------------------------------------------------
__global__ __launch_bounds__(256)
void k_qout()
{
    const int ch = blockIdx.x, h = blockIdx.y, b = blockIdx.z;
    const int tid = threadIdx.x;

    __shared__ float ctx[32][32];
    #pragma unroll
    for (int i = tid; i < 1024; i += 256)
        ctx[i >> 5][i & 31] = g_ctx[(b * HEADS + h) * 1024 + i];
    __syncthreads();

    const float* qbase = g_qkv  + ((size_t)b * O3  + h * DH) * NPIX;
    float*       obase = g_attn + ((size_t)b * HID + h * DH) * NPIX;
    const float scale = 0.17677669529663687f;   // 32^-0.5

    #pragma unroll 1
    for (int i = 0; i < 4; i++) {
        const int n = ch * 1024 + i * 256 + tid;
        float q[32];
        float m = -1e30f;
        #pragma unroll
        for (int dd = 0; dd < 32; dd++) {
            q[dd] = qbase[(size_t)dd * NPIX + n];
            m = fmaxf(m, q[dd]);
        }
        float s = 0.f;
        #pragma unroll
        for (int dd = 0; dd < 32; dd++) { q[dd] = __expf(q[dd] - m); s += q[dd]; }
        const float inv = scale / s;
        #pragma unroll
        for (int dd = 0; dd < 32; dd++) q[dd] *= inv;

        #pragma unroll
        for (int ee = 0; ee < 32; ee++) {
            float o = 0.f;
            #pragma unroll
            for (int dd = 0; dd < 32; dd++) o += ctx[dd][ee] * q[dd];
            obase[(size_t)ee * NPIX + n] = o;
        }
    }
}

// ---------------------------------------------------------------------------
// K4: in-place GroupNorm (per-batch stats) + per-channel affine
// ---------------------------------------------------------------------------
__global__ __launch_bounds__(256)
void k_gn(float* __restrict__ out,
          const float* __restrict__ gn_w,
          const float* __restrict__ gn_b)
{
    const size_t gid  = (size_t)blockIdx.x * blockDim.x + threadIdx.x;
    const size_t base = gid * 4;
    const int b = (int)(base >> 20);
    const int c = (int)((base >> 12) & 255);

    const float invN = 1.f / (256.f * 4096.f);
    const float mean = g_stats[2 * b + 0] * invN;
    const float var  = g_stats[2 * b + 1] * invN - mean * mean;
    const float r    = rsqrtf(var + EPS);
    const float w    = gn_w[c] * r;
    const float bb   = gn_b[c] - mean * w;

    float4 v = *(float4*)&out[base];
    v.x = v.x * w + bb;
    v.y = v.y * w + bb;
    v.z = v.z * w + bb;
    v.w = v.w * w + bb;
    *(float4*)&out[base] = v;
}

// ---------------------------------------------------------------------------
// Launch
// ---------------------------------------------------------------------------
extern "C" void kernel_launch(void* const* d_in, const int* in_sizes, int n_in,
                              void* d_out, int out_size)
{
    const float* x     = (const float*)d_in[0];
    const float* w_qkv = (const float*)d_in[1];
    const float* w_out = (const float*)d_in[2];
    const float* b_out = (const float*)d_in[3];
    const float* gn_w  = (const float*)d_in[4];
    const float* gn_b  = (const float*)d_in[5];
    float* out = (float*)d_out;

    float *p_qkv, *p_attn;
    cudaGetSymbolAddress((void**)&p_qkv,  g_qkv);
    cudaGetSymbolAddress((void**)&p_attn, g_attn);

    cudaFuncSetAttribute(k_mma<CIN, O3, false>,
                         cudaFuncAttributeMaxDynamicSharedMemorySize, MMA_SMEM);
    cudaFuncSetAttribute(k_mma<HID, CIN, true>,
                         cudaFuncAttributeMaxDynamicSharedMemorySize, MMA_SMEM);
    cudaFuncSetAttribute(k_ctx,
                         cudaFuncAttributeMaxDynamicSharedMemorySize, CTX_SMEM);

    // K0: zero stats + ctx
    k_zero<<<(ZERO_N + 255) / 256, 256>>>();

    // K1: QKV projection  [384,256] x [256,4096] per batch (tf32 HMMA)
    k_mma<CIN, O3, false>
        <<<dim3(NPIX / 128, O3 / 128, BATCH), 256, MMA_SMEM>>>(w_qkv, x, p_qkv, nullptr);

    // K2: attention core
    k_kstats<<<dim3(HEADS, BATCH), 1024>>>();
    k_ctx   <<<dim3(8, HEADS, BATCH), 256, CTX_SMEM>>>();
    k_qout  <<<dim3(4, HEADS, BATCH), 256>>>();

    // K3: output projection + bias + stats  [256,128] x [128,4096] per batch
    k_mma<HID, CIN, true>
        <<<dim3(NPIX / 128, CIN / 128, BATCH), 256, MMA_SMEM>>>(w_out, p_attn, out, b_out);

    // K4: GroupNorm normalize in place
    k_gn<<<(BATCH * CIN * NPIX / 4) / 256, 256>>>(out, gn_w, gn_b);
}